// round 1
// baseline (speedup 1.0000x reference)
#include <cuda_runtime.h>
#include <math.h>

// Problem constants
#define BSZ   16384
#define FDIM  1024
#define HDIM  64
#define DDIM  256
#define NEXP  4
#define NH    256           // NEXP * HDIM (same for all 3 groups)
#define BD    (BSZ * DDIM)  // 4194304

// Scratch (device globals — no allocation allowed)
__device__ float g_h[3][(size_t)BSZ * NH];   // relu(x @ W1 + b1) per group  (~50MB)
__device__ float g_gA[BSZ * 8];
__device__ float g_gS[BSZ * 12];
__device__ float g_gB[BSZ * 8];

// ---------------------------------------------------------------------------
// Gates: logits = x @ Wg + bg, softmax over G columns. Warp per row.
// Wg staged transposed in smem: wT[g*1024 + f] -> conflict-free lane reads.
// ---------------------------------------------------------------------------
#define GATES_SMEM ((8192 + 8192 + 12288) * 4)

__global__ __launch_bounds__(256) void gates_kernel(
    const float* __restrict__ xA, const float* __restrict__ xS, const float* __restrict__ xB,
    const float* __restrict__ WgA, const float* __restrict__ bgA,
    const float* __restrict__ WgB, const float* __restrict__ bgB,
    const float* __restrict__ WgS, const float* __restrict__ bgS)
{
    extern __shared__ float sg[];
    float* wA = sg;          // [8][1024]
    float* wB = sg + 8192;   // [8][1024]
    float* wS = sg + 16384;  // [12][1024]

    int t = threadIdx.x;
    // stage transposed
    for (int i = t; i < 8192; i += 256) {
        int f = i >> 3, g = i & 7;
        wA[g * 1024 + f] = WgA[i];
        wB[g * 1024 + f] = WgB[i];
    }
    for (int i = t; i < 12288; i += 256) {
        int f = i / 12, g = i % 12;
        wS[g * 1024 + f] = WgS[i];
    }
    __syncthreads();

    int warp = t >> 5, lane = t & 31;

    for (int rr = 0; rr < 8; rr++) {
        int b = blockIdx.x * 64 + warp * 8 + rr;

        float aA[8], aB[8], aS[12];
        #pragma unroll
        for (int g = 0; g < 8; g++) { aA[g] = 0.f; aB[g] = 0.f; }
        #pragma unroll
        for (int g = 0; g < 12; g++) aS[g] = 0.f;

        const float* xArow = xA + (size_t)b * FDIM;
        const float* xSrow = xS + (size_t)b * FDIM;
        const float* xBrow = xB + (size_t)b * FDIM;

        for (int f = lane; f < FDIM; f += 32) {
            float va = xArow[f];
            float vs = xSrow[f];
            float vb = xBrow[f];
            #pragma unroll
            for (int g = 0; g < 8; g++) {
                aA[g] = fmaf(va, wA[g * 1024 + f], aA[g]);
                aB[g] = fmaf(vb, wB[g * 1024 + f], aB[g]);
            }
            #pragma unroll
            for (int g = 0; g < 12; g++)
                aS[g] = fmaf(vs, wS[g * 1024 + f], aS[g]);
        }

        // warp xor-reduction (all lanes end with full sum)
        #pragma unroll
        for (int g = 0; g < 8; g++) {
            #pragma unroll
            for (int o = 16; o > 0; o >>= 1) {
                aA[g] += __shfl_xor_sync(0xffffffffu, aA[g], o);
                aB[g] += __shfl_xor_sync(0xffffffffu, aB[g], o);
            }
        }
        #pragma unroll
        for (int g = 0; g < 12; g++) {
            #pragma unroll
            for (int o = 16; o > 0; o >>= 1)
                aS[g] += __shfl_xor_sync(0xffffffffu, aS[g], o);
        }

        if (lane == 0) {
            // softmax A
            {
                float l[8], m = -1e30f, s = 0.f;
                #pragma unroll
                for (int g = 0; g < 8; g++) { l[g] = aA[g] + bgA[g]; m = fmaxf(m, l[g]); }
                #pragma unroll
                for (int g = 0; g < 8; g++) { l[g] = expf(l[g] - m); s += l[g]; }
                float inv = 1.f / s;
                #pragma unroll
                for (int g = 0; g < 8; g++) g_gA[b * 8 + g] = l[g] * inv;
            }
            // softmax B
            {
                float l[8], m = -1e30f, s = 0.f;
                #pragma unroll
                for (int g = 0; g < 8; g++) { l[g] = aB[g] + bgB[g]; m = fmaxf(m, l[g]); }
                #pragma unroll
                for (int g = 0; g < 8; g++) { l[g] = expf(l[g] - m); s += l[g]; }
                float inv = 1.f / s;
                #pragma unroll
                for (int g = 0; g < 8; g++) g_gB[b * 8 + g] = l[g] * inv;
            }
            // softmax S
            {
                float l[12], m = -1e30f, s = 0.f;
                #pragma unroll
                for (int g = 0; g < 12; g++) { l[g] = aS[g] + bgS[g]; m = fmaxf(m, l[g]); }
                #pragma unroll
                for (int g = 0; g < 12; g++) { l[g] = expf(l[g] - m); s += l[g]; }
                float inv = 1.f / s;
                #pragma unroll
                for (int g = 0; g < 12; g++) g_gS[b * 12 + g] = l[g] * inv;
            }
        }
    }
}

// ---------------------------------------------------------------------------
// Phase 1: h = relu(X @ W1flat + b1) per group. 128x128x8 tiled SGEMM,
// 8x8 microtile per thread, 256 threads. W1 is [E,F,H]; column c=(e*64+h)
// of the flat [F,256] matrix lives at e*F*H + f*H + h.
// grid = (2, 128, 3)
// ---------------------------------------------------------------------------
__global__ __launch_bounds__(256, 2) void phase1_kernel(
    const float* __restrict__ xA, const float* __restrict__ xS, const float* __restrict__ xB,
    const float* __restrict__ W1A, const float* __restrict__ b1A,
    const float* __restrict__ W1S, const float* __restrict__ b1S,
    const float* __restrict__ W1B, const float* __restrict__ b1B)
{
    int z = blockIdx.z;
    const float* X  = (z == 0) ? xA  : (z == 1) ? xS  : xB;
    const float* W1 = (z == 0) ? W1A : (z == 1) ? W1S : W1B;
    const float* b1 = (z == 0) ? b1A : (z == 1) ? b1S : b1B;
    float* Hout = g_h[z];

    __shared__ float As[8][128];
    __shared__ float Bs[8][128];

    int m0 = blockIdx.y * 128;
    int n0 = blockIdx.x * 128;
    int t  = threadIdx.x;
    int tx = t & 15, ty = t >> 4;

    float acc[8][8];
    #pragma unroll
    for (int i = 0; i < 8; i++)
        #pragma unroll
        for (int j = 0; j < 8; j++) acc[i][j] = 0.f;

    int arow = t >> 1;
    int acol = (t & 1) * 4;

    // precompute W1 column bases for the 4 B-tile elements this thread loads
    int bK[4], bN[4];
    size_t bBase[4];
    #pragma unroll
    for (int i = 0; i < 4; i++) {
        int idx = t + 256 * i;
        bK[i] = idx >> 7;
        bN[i] = idx & 127;
        int c = n0 + bN[i];
        bBase[i] = (size_t)(c >> 6) * FDIM * HDIM + (size_t)(c & 63);
    }

    for (int k0 = 0; k0 < FDIM; k0 += 8) {
        float4 av = *(const float4*)&X[(size_t)(m0 + arow) * FDIM + k0 + acol];
        float bv[4];
        #pragma unroll
        for (int i = 0; i < 4; i++)
            bv[i] = W1[bBase[i] + (size_t)(k0 + bK[i]) * HDIM];

        __syncthreads();
        As[acol + 0][arow] = av.x;
        As[acol + 1][arow] = av.y;
        As[acol + 2][arow] = av.z;
        As[acol + 3][arow] = av.w;
        #pragma unroll
        for (int i = 0; i < 4; i++) Bs[bK[i]][bN[i]] = bv[i];
        __syncthreads();

        #pragma unroll
        for (int k = 0; k < 8; k++) {
            float a[8], b[8];
            float4 a0 = *(const float4*)&As[k][ty * 8];
            float4 a1 = *(const float4*)&As[k][ty * 8 + 4];
            float4 b0 = *(const float4*)&Bs[k][tx * 8];
            float4 b1v = *(const float4*)&Bs[k][tx * 8 + 4];
            a[0]=a0.x; a[1]=a0.y; a[2]=a0.z; a[3]=a0.w;
            a[4]=a1.x; a[5]=a1.y; a[6]=a1.z; a[7]=a1.w;
            b[0]=b0.x; b[1]=b0.y; b[2]=b0.z; b[3]=b0.w;
            b[4]=b1v.x; b[5]=b1v.y; b[6]=b1v.z; b[7]=b1v.w;
            #pragma unroll
            for (int i = 0; i < 8; i++)
                #pragma unroll
                for (int j = 0; j < 8; j++)
                    acc[i][j] = fmaf(a[i], b[j], acc[i][j]);
        }
    }

    #pragma unroll
    for (int i = 0; i < 8; i++) {
        int r = m0 + ty * 8 + i;
        #pragma unroll
        for (int j = 0; j < 8; j++) {
            int c = n0 + tx * 8 + j;
            float v = acc[i][j] + b1[c];
            Hout[(size_t)r * NH + c] = fmaxf(v, 0.f);
        }
    }
}

// ---------------------------------------------------------------------------
// Phase 2: per 32-row tile, compute all 12 expert outputs
// y = relu(h_e @ W2_e + b2_e) in registers and accumulate gate-weighted
// sums into outA/outS/outB. Nothing intermediate touches HBM.
// 256 threads: thread owns rows r0..r0+3 (r0=(t>>5)*4) and cols
// (t&31)*8 .. +7.
// ---------------------------------------------------------------------------
#define P2_SMEM ((3 * 32 * 256 + 64 * 256 + 32 * 8 + 32 * 12 + 32 * 8) * 4)

__global__ __launch_bounds__(256, 1) void phase2_kernel(
    const float* __restrict__ W2A, const float* __restrict__ b2A,
    const float* __restrict__ W2S, const float* __restrict__ b2S,
    const float* __restrict__ W2B, const float* __restrict__ b2B,
    float* __restrict__ out)
{
    extern __shared__ float sm[];
    float* hs  = sm;                  // [3][32][256]
    float* w2s = sm + 3 * 32 * 256;   // [64][256]
    float* gAs = w2s + 64 * 256;      // [32][8]
    float* gSs = gAs + 32 * 8;        // [32][12]
    float* gBs = gSs + 32 * 12;       // [32][8]

    int t  = threadIdx.x;
    int b0 = blockIdx.x * 32;

    // stage h tiles (float4, coalesced)
    #pragma unroll
    for (int z = 0; z < 3; z++) {
        const float4* src = (const float4*)(g_h[z] + (size_t)b0 * NH);
        float4* dst = (float4*)(hs + z * 8192);
        for (int i = t; i < 8192 / 4; i += 256) dst[i] = src[i];
    }
    // stage gates
    for (int i = t; i < 32 * 8; i += 256)  gAs[i] = g_gA[b0 * 8 + i];
    for (int i = t; i < 32 * 12; i += 256) gSs[i] = g_gS[b0 * 12 + i];
    for (int i = t; i < 32 * 8; i += 256)  gBs[i] = g_gB[b0 * 8 + i];

    float accA[32], accS[32], accB[32];
    #pragma unroll
    for (int i = 0; i < 32; i++) { accA[i] = 0.f; accS[i] = 0.f; accB[i] = 0.f; }

    int colb = (t & 31) * 8;
    int r0   = (t >> 5) * 4;

    #pragma unroll
    for (int grp = 0; grp < 3; grp++) {
        const float* W2  = (grp == 0) ? W2A : (grp == 1) ? W2S : W2B;
        const float* b2  = (grp == 0) ? b2A : (grp == 1) ? b2S : b2B;
        const float* hsg = hs + grp * 8192;

        for (int e = 0; e < NEXP; e++) {
            __syncthreads();
            {
                const float4* src = (const float4*)(W2 + (size_t)e * HDIM * DDIM);
                float4* dst = (float4*)w2s;
                for (int i = t; i < (HDIM * DDIM) / 4; i += 256) dst[i] = src[i];
            }
            __syncthreads();

            float y[4][8];
            #pragma unroll
            for (int i = 0; i < 4; i++)
                #pragma unroll
                for (int j = 0; j < 8; j++) y[i][j] = 0.f;

            #pragma unroll 4
            for (int h = 0; h < HDIM; h++) {
                float wr[8];
                float4 w0 = *(const float4*)&w2s[h * 256 + colb];
                float4 w1v = *(const float4*)&w2s[h * 256 + colb + 4];
                wr[0]=w0.x; wr[1]=w0.y; wr[2]=w0.z; wr[3]=w0.w;
                wr[4]=w1v.x; wr[5]=w1v.y; wr[6]=w1v.z; wr[7]=w1v.w;
                #pragma unroll
                for (int i = 0; i < 4; i++) {
                    float hv = hsg[(r0 + i) * 256 + e * HDIM + h];  // warp broadcast
                    #pragma unroll
                    for (int j = 0; j < 8; j++)
                        y[i][j] = fmaf(hv, wr[j], y[i][j]);
                }
            }

            // bias + relu + gate-weighted accumulation
            #pragma unroll
            for (int j = 0; j < 8; j++) {
                float bb = b2[e * DDIM + colb + j];
                #pragma unroll
                for (int i = 0; i < 4; i++) {
                    float v = fmaxf(y[i][j] + bb, 0.f);
                    int r = r0 + i;
                    if (grp == 0) {            // group A: experts 0..3 of outA, outS
                        accA[i * 8 + j] = fmaf(gAs[r * 8 + e],      v, accA[i * 8 + j]);
                        accS[i * 8 + j] = fmaf(gSs[r * 12 + e],     v, accS[i * 8 + j]);
                    } else if (grp == 1) {     // group S: experts 4..7 of all three
                        accA[i * 8 + j] = fmaf(gAs[r * 8 + 4 + e],  v, accA[i * 8 + j]);
                        accS[i * 8 + j] = fmaf(gSs[r * 12 + 4 + e], v, accS[i * 8 + j]);
                        accB[i * 8 + j] = fmaf(gBs[r * 8 + 4 + e],  v, accB[i * 8 + j]);
                    } else {                   // group B: experts 8..11 of outS, 0..3 of outB
                        accS[i * 8 + j] = fmaf(gSs[r * 12 + 8 + e], v, accS[i * 8 + j]);
                        accB[i * 8 + j] = fmaf(gBs[r * 8 + e],      v, accB[i * 8 + j]);
                    }
                }
            }
        }
    }

    // store outputs (coalesced)
    #pragma unroll
    for (int i = 0; i < 4; i++) {
        size_t r = (size_t)(b0 + r0 + i);
        #pragma unroll
        for (int j = 0; j < 8; j++) {
            size_t c = colb + j;
            out[r * DDIM + c]              = accA[i * 8 + j];
            out[(size_t)BD + r * DDIM + c] = accS[i * 8 + j];
            out[2ull * BD + r * DDIM + c]  = accB[i * 8 + j];
        }
    }
}

// ---------------------------------------------------------------------------
extern "C" void kernel_launch(void* const* d_in, const int* in_sizes, int n_in,
                              void* d_out, int out_size)
{
    const float* xA  = (const float*)d_in[0];
    const float* xS  = (const float*)d_in[1];
    const float* xB  = (const float*)d_in[2];
    const float* W1A = (const float*)d_in[3];
    const float* b1A = (const float*)d_in[4];
    const float* W2A = (const float*)d_in[5];
    const float* b2A = (const float*)d_in[6];
    const float* W1S = (const float*)d_in[7];
    const float* b1S = (const float*)d_in[8];
    const float* W2S = (const float*)d_in[9];
    const float* b2S = (const float*)d_in[10];
    const float* W1B = (const float*)d_in[11];
    const float* b1B = (const float*)d_in[12];
    const float* W2B = (const float*)d_in[13];
    const float* b2B = (const float*)d_in[14];
    const float* WgA = (const float*)d_in[15];
    const float* bgA = (const float*)d_in[16];
    const float* WgB = (const float*)d_in[17];
    const float* bgB = (const float*)d_in[18];
    const float* WgS = (const float*)d_in[19];
    const float* bgS = (const float*)d_in[20];
    float* out = (float*)d_out;

    cudaFuncSetAttribute(gates_kernel,  cudaFuncAttributeMaxDynamicSharedMemorySize, GATES_SMEM);
    cudaFuncSetAttribute(phase2_kernel, cudaFuncAttributeMaxDynamicSharedMemorySize, P2_SMEM);

    gates_kernel<<<BSZ / 64, 256, GATES_SMEM>>>(xA, xS, xB, WgA, bgA, WgB, bgB, WgS, bgS);
    phase1_kernel<<<dim3(2, 128, 3), 256>>>(xA, xS, xB, W1A, b1A, W1S, b1S, W1B, b1B);
    phase2_kernel<<<BSZ / 32, 256, P2_SMEM>>>(W2A, b2A, W2S, b2S, W2B, b2B, out);
}

// round 6
// speedup vs baseline: 1.6920x; 1.6920x over previous
#include <cuda_runtime.h>
#include <cuda_bf16.h>
#include <cstdint>
#include <cstddef>
#include <math.h>

// Problem constants
#define BSZ   16384
#define FDIM  1024
#define HDIM  64
#define DDIM  256
#define NEXP  4
#define NH    256
#define BD    (BSZ * DDIM)

// ---------------------------------------------------------------------------
// Scratch (device globals — no allocation allowed)
// ---------------------------------------------------------------------------
__device__ float g_h[3][(size_t)BSZ * NH];          // relu(x@W1+b1), fp32 (50MB)
__device__ float g_gA[BSZ * 8];
__device__ float g_gS[BSZ * 12];
__device__ float g_gB[BSZ * 8];

// bf16-split W1, transposed to [N=256][K=1024] rows
__device__ __align__(16) __nv_bfloat16 g_wh[3][256 * 1024];
__device__ __align__(16) __nv_bfloat16 g_wl[3][256 * 1024];
// bf16-split activations [B][1024]
__device__ __align__(16) __nv_bfloat16 g_xh[3][(size_t)BSZ * FDIM];
__device__ __align__(16) __nv_bfloat16 g_xl[3][(size_t)BSZ * FDIM];

// ---------------------------------------------------------------------------
// Helpers
// ---------------------------------------------------------------------------
__device__ __forceinline__ uint32_t smem_u32(const void* p) {
    uint32_t a;
    asm("{ .reg .u64 t; cvta.to.shared.u64 t, %1; cvt.u32.u64 %0, t; }" : "=r"(a) : "l"(p));
    return a;
}
__device__ __forceinline__ void cp16(uint32_t dst, const void* src) {
    asm volatile("cp.async.cg.shared.global [%0], [%1], 16;" :: "r"(dst), "l"(src));
}
__device__ __forceinline__ void cp_commit() { asm volatile("cp.async.commit_group;" ::: "memory"); }
template <int N>
__device__ __forceinline__ void cp_wait() { asm volatile("cp.async.wait_group %0;" :: "n"(N) : "memory"); }

__device__ __forceinline__ void ldsm4(uint32_t* r, uint32_t addr) {
    asm volatile("ldmatrix.sync.aligned.m8n8.x4.shared.b16 {%0,%1,%2,%3}, [%4];"
                 : "=r"(r[0]), "=r"(r[1]), "=r"(r[2]), "=r"(r[3]) : "r"(addr));
}
__device__ __forceinline__ void mma16816(float* d, const uint32_t* a, const uint32_t* b) {
    asm volatile(
        "mma.sync.aligned.m16n8k16.row.col.f32.bf16.bf16.f32 "
        "{%0,%1,%2,%3}, {%4,%5,%6,%7}, {%8,%9}, {%0,%1,%2,%3};"
        : "+f"(d[0]), "+f"(d[1]), "+f"(d[2]), "+f"(d[3])
        : "r"(a[0]), "r"(a[1]), "r"(a[2]), "r"(a[3]), "r"(b[0]), "r"(b[1]));
}
__device__ __forceinline__ uint32_t packbf(float x, float y) {
    __nv_bfloat16 hx = __float2bfloat16(x);
    __nv_bfloat16 hy = __float2bfloat16(y);
    return ((uint32_t)__bfloat16_as_ushort(hy) << 16) | __bfloat16_as_ushort(hx);
}

// ---------------------------------------------------------------------------
// wsplit: W1 [E,F,H] -> transposed [256][1024] hi/lo bf16
// ---------------------------------------------------------------------------
__global__ __launch_bounds__(256) void wsplit_kernel(
    const float* __restrict__ W1A, const float* __restrict__ W1S, const float* __restrict__ W1B)
{
    int id = blockIdx.x * 256 + threadIdx.x;     // 0..786431
    int z = id >> 18;
    int r = id & 262143;
    int c = r >> 10, f = r & 1023;
    const float* W = (z == 0) ? W1A : (z == 1) ? W1S : W1B;
    float v = W[(size_t)(c >> 6) * 65536 + f * 64 + (c & 63)];
    __nv_bfloat16 h = __float2bfloat16(v);
    g_wh[z][c * 1024 + f] = h;
    g_wl[z][c * 1024 + f] = __float2bfloat16(v - __bfloat162float(h));
}

// ---------------------------------------------------------------------------
// xsplit_gates: stream x once; emit xh/xl bf16 and gate softmax.
// Warp per row. Wg transposed in smem [G][1024].
// grid = (2048, 3), block = 256, dyn smem = 12*1024*4
// ---------------------------------------------------------------------------
template <int G>
__device__ __forceinline__ void xsg_row(
    const float* __restrict__ xrow, __nv_bfloat16* __restrict__ hrow,
    __nv_bfloat16* __restrict__ lrow, const float* __restrict__ wT,
    const float* __restrict__ bg, float* __restrict__ gout, int lane)
{
    float acc[G];
    #pragma unroll
    for (int g = 0; g < G; g++) acc[g] = 0.f;

    #pragma unroll
    for (int j = 0; j < 8; j++) {
        int f0 = j * 128 + lane * 4;
        float4 xv = *(const float4*)(xrow + f0);
        // split + store
        uint32_t h0 = packbf(xv.x, xv.y), h1 = packbf(xv.z, xv.w);
        float rx = xv.x - __bfloat162float(__ushort_as_bfloat16((uint16_t)(h0 & 0xffff)));
        float ry = xv.y - __bfloat162float(__ushort_as_bfloat16((uint16_t)(h0 >> 16)));
        float rz = xv.z - __bfloat162float(__ushort_as_bfloat16((uint16_t)(h1 & 0xffff)));
        float rw = xv.w - __bfloat162float(__ushort_as_bfloat16((uint16_t)(h1 >> 16)));
        uint32_t l0 = packbf(rx, ry), l1 = packbf(rz, rw);
        *(uint2*)(hrow + f0) = make_uint2(h0, h1);
        *(uint2*)(lrow + f0) = make_uint2(l0, l1);
        #pragma unroll
        for (int g = 0; g < G; g++) {
            float4 wv = *(const float4*)(wT + g * 1024 + f0);
            acc[g] += xv.x * wv.x + xv.y * wv.y + xv.z * wv.z + xv.w * wv.w;
        }
    }
    #pragma unroll
    for (int g = 0; g < G; g++) {
        #pragma unroll
        for (int o = 16; o > 0; o >>= 1) acc[g] += __shfl_xor_sync(0xffffffffu, acc[g], o);
    }
    if (lane == 0) {
        float l[G], m = -1e30f, s = 0.f;
        #pragma unroll
        for (int g = 0; g < G; g++) { l[g] = acc[g] + __ldg(&bg[g]); m = fmaxf(m, l[g]); }
        #pragma unroll
        for (int g = 0; g < G; g++) { l[g] = expf(l[g] - m); s += l[g]; }
        float inv = 1.f / s;
        #pragma unroll
        for (int g = 0; g < G; g++) gout[g] = l[g] * inv;
    }
}

__global__ __launch_bounds__(256) void xsplit_gates_kernel(
    const float* __restrict__ xA, const float* __restrict__ xS, const float* __restrict__ xB,
    const float* __restrict__ WgA, const float* __restrict__ WgS, const float* __restrict__ WgB,
    const float* __restrict__ bgA, const float* __restrict__ bgS, const float* __restrict__ bgB)
{
    extern __shared__ float wT[];
    int tid = threadIdx.x;
    int z = blockIdx.y;
    int G = (z == 1) ? 12 : 8;
    const float* X  = (z == 0) ? xA  : (z == 1) ? xS  : xB;
    const float* Wg = (z == 0) ? WgA : (z == 1) ? WgS : WgB;
    const float* bg = (z == 0) ? bgA : (z == 1) ? bgS : bgB;

    for (int i = tid; i < G * 1024; i += 256) {
        int f = i / G, g = i - f * G;
        wT[g * 1024 + f] = Wg[i];
    }
    __syncthreads();

    int wid = tid >> 5, lane = tid & 31;
    int row = blockIdx.x * 8 + wid;
    const float* xrow = X + (size_t)row * FDIM;
    __nv_bfloat16* hrow = g_xh[z] + (size_t)row * FDIM;
    __nv_bfloat16* lrow = g_xl[z] + (size_t)row * FDIM;

    if (z == 0)      xsg_row<8 >(xrow, hrow, lrow, wT, bg, g_gA + row * 8,  lane);
    else if (z == 1) xsg_row<12>(xrow, hrow, lrow, wT, bg, g_gS + row * 12, lane);
    else             xsg_row<8 >(xrow, hrow, lrow, wT, bg, g_gB + row * 8,  lane);
}

// ---------------------------------------------------------------------------
// Phase 1: bf16-split GEMM via mma.sync m16n8k16.
// CTA tile M=128, N=128, K-chunk=64. 8 warps (4m x 2n), warp tile 32x64.
// smem per stage: Ah/Al/Bh/Bl each [128 rows][128B] SW128-swizzled = 64KB;
// 2 stages = 128KB. grid = (2, 128, 3).
// ---------------------------------------------------------------------------
#define P1_STAGE 65536
#define P1_SMEM  (2 * P1_STAGE)

__global__ __launch_bounds__(256) void phase1_mma_kernel(
    const float* __restrict__ b1A, const float* __restrict__ b1S, const float* __restrict__ b1B)
{
    extern __shared__ char smem[];
    uint32_t sb = smem_u32(smem);

    int tid  = threadIdx.x;
    int w    = tid >> 5;
    int lane = tid & 31;
    int wm   = w & 3;         // 4 m-tiles of 32
    int wn   = w >> 2;        // 2 n-tiles of 64
    int z    = blockIdx.z;
    int m0   = blockIdx.y * 128;
    int n0   = blockIdx.x * 128;

    const __nv_bfloat16* Xh = g_xh[z];
    const __nv_bfloat16* Xl = g_xl[z];
    const __nv_bfloat16* Wh = g_wh[z];
    const __nv_bfloat16* Wl = g_wl[z];
    const float* b1 = (z == 0) ? b1A : (z == 1) ? b1S : b1B;

    // cp.async task map: 4096 16B-chunks/stage, 16 per thread.
    // task = i*256+tid; part = task/1024 (Ah,Al,Bh,Bl); idx=task%1024;
    // row = idx/8; sub = idx%8.
    int trow[16], tsub[16], tpart[16];
    #pragma unroll
    for (int i = 0; i < 16; i++) {
        int task = i * 256 + tid;
        tpart[i] = task >> 10;
        int idx = task & 1023;
        trow[i] = idx >> 3;
        tsub[i] = idx & 7;
    }

    auto load_stage = [&](int s, int k0) {
        uint32_t base = sb + (uint32_t)s * P1_STAGE;
        #pragma unroll
        for (int i = 0; i < 16; i++) {
            int part = tpart[i], row = trow[i], sub = tsub[i];
            uint32_t dst = base + (uint32_t)part * 16384 + (uint32_t)(row * 128) +
                           (uint32_t)(((sub ^ (row & 7)) & 7) << 4);
            const __nv_bfloat16* src;
            if (part == 0)      src = Xh + (size_t)(m0 + row) * FDIM + k0 + sub * 8;
            else if (part == 1) src = Xl + (size_t)(m0 + row) * FDIM + k0 + sub * 8;
            else if (part == 2) src = Wh + (size_t)(n0 + row) * FDIM + k0 + sub * 8;
            else                src = Wl + (size_t)(n0 + row) * FDIM + k0 + sub * 8;
            cp16(dst, src);
        }
        cp_commit();
    };

    float D[2][8][4];
    #pragma unroll
    for (int mf = 0; mf < 2; mf++)
        #pragma unroll
        for (int nf = 0; nf < 8; nf++)
            #pragma unroll
            for (int k = 0; k < 4; k++) D[mf][nf][k] = 0.f;

    int q  = lane >> 3;   // quadrant within ldmatrix.x4
    int rr = lane & 7;

    load_stage(0, 0);

    for (int kc = 0; kc < 16; kc++) {
        int s = kc & 1;
        if (kc + 1 < 16) load_stage(s ^ 1, (kc + 1) * 64);
        if (kc + 1 < 16) cp_wait<1>(); else cp_wait<0>();
        __syncthreads();

        uint32_t sA = sb + (uint32_t)s * P1_STAGE;            // Ah
        uint32_t sAl = sA + 16384;
        uint32_t sBh = sA + 32768;
        uint32_t sBl = sA + 49152;

        #pragma unroll
        for (int kk = 0; kk < 4; kk++) {
            uint32_t Bh_[16], Bl_[16];
            #pragma unroll
            for (int bg = 0; bg < 4; bg++) {
                int rowb = wn * 64 + (bg * 2 + q / 2) * 8 + rr;
                int ch = kk * 2 + (q & 1);
                uint32_t off = (uint32_t)(rowb * 128 + ((ch ^ (rowb & 7)) << 4));
                ldsm4(&Bh_[bg * 4], sBh + off);
                ldsm4(&Bl_[bg * 4], sBl + off);
            }
            uint32_t Af_[2][4];
            #pragma unroll
            for (int mf = 0; mf < 2; mf++) {
                int rowa = wm * 32 + mf * 16 + (q & 1) * 8 + rr;
                int ch = kk * 2 + (q >> 1);
                uint32_t off = (uint32_t)(rowa * 128 + ((ch ^ (rowa & 7)) << 4));
                ldsm4(Af_[mf], sA + off);
            }
            #pragma unroll
            for (int mf = 0; mf < 2; mf++)
                #pragma unroll
                for (int nf = 0; nf < 8; nf++) {
                    mma16816(D[mf][nf], Af_[mf], &Bh_[nf * 2]);
                    mma16816(D[mf][nf], Af_[mf], &Bl_[nf * 2]);
                }
            // reload A as lo-half, multiply with Bh
            #pragma unroll
            for (int mf = 0; mf < 2; mf++) {
                int rowa = wm * 32 + mf * 16 + (q & 1) * 8 + rr;
                int ch = kk * 2 + (q >> 1);
                uint32_t off = (uint32_t)(rowa * 128 + ((ch ^ (rowa & 7)) << 4));
                ldsm4(Af_[mf], sAl + off);
            }
            #pragma unroll
            for (int mf = 0; mf < 2; mf++)
                #pragma unroll
                for (int nf = 0; nf < 8; nf++)
                    mma16816(D[mf][nf], Af_[mf], &Bh_[nf * 2]);
        }
        __syncthreads();
    }

    // Epilogue: bias + relu -> g_h
    float* Hout = g_h[z];
    #pragma unroll
    for (int nf = 0; nf < 8; nf++) {
        int col = n0 + wn * 64 + nf * 8 + (lane & 3) * 2;
        float bias0 = __ldg(&b1[col]);
        float bias1 = __ldg(&b1[col + 1]);
        #pragma unroll
        for (int mf = 0; mf < 2; mf++) {
            int row0 = m0 + wm * 32 + mf * 16 + (lane >> 2);
            float2 v0 = make_float2(fmaxf(D[mf][nf][0] + bias0, 0.f),
                                    fmaxf(D[mf][nf][1] + bias1, 0.f));
            float2 v1 = make_float2(fmaxf(D[mf][nf][2] + bias0, 0.f),
                                    fmaxf(D[mf][nf][3] + bias1, 0.f));
            *(float2*)(Hout + (size_t)row0 * NH + col)       = v0;
            *(float2*)(Hout + (size_t)(row0 + 8) * NH + col) = v1;
        }
    }
}

// ---------------------------------------------------------------------------
// Phase 2 (SIMT, unchanged from R1-passing version)
// ---------------------------------------------------------------------------
#define P2_SMEM ((3 * 32 * 256 + 64 * 256 + 32 * 8 + 32 * 12 + 32 * 8) * 4)

__global__ __launch_bounds__(256, 1) void phase2_kernel(
    const float* __restrict__ W2A, const float* __restrict__ b2A,
    const float* __restrict__ W2S, const float* __restrict__ b2S,
    const float* __restrict__ W2B, const float* __restrict__ b2B,
    float* __restrict__ out)
{
    extern __shared__ float sm[];
    float* hs  = sm;                  // [3][32][256]
    float* w2s = sm + 3 * 32 * 256;   // [64][256]
    float* gAs = w2s + 64 * 256;      // [32][8]
    float* gSs = gAs + 32 * 8;        // [32][12]
    float* gBs = gSs + 32 * 12;       // [32][8]

    int t  = threadIdx.x;
    int b0 = blockIdx.x * 32;

    #pragma unroll
    for (int z = 0; z < 3; z++) {
        const float4* src = (const float4*)(g_h[z] + (size_t)b0 * NH);
        float4* dst = (float4*)(hs + z * 8192);
        for (int i = t; i < 8192 / 4; i += 256) dst[i] = src[i];
    }
    for (int i = t; i < 32 * 8; i += 256)  gAs[i] = g_gA[b0 * 8 + i];
    for (int i = t; i < 32 * 12; i += 256) gSs[i] = g_gS[b0 * 12 + i];
    for (int i = t; i < 32 * 8; i += 256)  gBs[i] = g_gB[b0 * 8 + i];

    float accA[32], accS[32], accB[32];
    #pragma unroll
    for (int i = 0; i < 32; i++) { accA[i] = 0.f; accS[i] = 0.f; accB[i] = 0.f; }

    int colb = (t & 31) * 8;
    int r0   = (t >> 5) * 4;

    #pragma unroll
    for (int grp = 0; grp < 3; grp++) {
        const float* W2  = (grp == 0) ? W2A : (grp == 1) ? W2S : W2B;
        const float* b2  = (grp == 0) ? b2A : (grp == 1) ? b2S : b2B;
        const float* hsg = hs + grp * 8192;

        for (int e = 0; e < NEXP; e++) {
            __syncthreads();
            {
                const float4* src = (const float4*)(W2 + (size_t)e * HDIM * DDIM);
                float4* dst = (float4*)w2s;
                for (int i = t; i < (HDIM * DDIM) / 4; i += 256) dst[i] = src[i];
            }
            __syncthreads();

            float y[4][8];
            #pragma unroll
            for (int i = 0; i < 4; i++)
                #pragma unroll
                for (int j = 0; j < 8; j++) y[i][j] = 0.f;

            #pragma unroll 4
            for (int h = 0; h < HDIM; h++) {
                float wr[8];
                float4 w0 = *(const float4*)&w2s[h * 256 + colb];
                float4 w1v = *(const float4*)&w2s[h * 256 + colb + 4];
                wr[0]=w0.x; wr[1]=w0.y; wr[2]=w0.z; wr[3]=w0.w;
                wr[4]=w1v.x; wr[5]=w1v.y; wr[6]=w1v.z; wr[7]=w1v.w;
                #pragma unroll
                for (int i = 0; i < 4; i++) {
                    float hv = hsg[(r0 + i) * 256 + e * HDIM + h];
                    #pragma unroll
                    for (int j = 0; j < 8; j++)
                        y[i][j] = fmaf(hv, wr[j], y[i][j]);
                }
            }

            #pragma unroll
            for (int j = 0; j < 8; j++) {
                float bb = b2[e * DDIM + colb + j];
                #pragma unroll
                for (int i = 0; i < 4; i++) {
                    float v = fmaxf(y[i][j] + bb, 0.f);
                    int r = r0 + i;
                    if (grp == 0) {
                        accA[i * 8 + j] = fmaf(gAs[r * 8 + e],      v, accA[i * 8 + j]);
                        accS[i * 8 + j] = fmaf(gSs[r * 12 + e],     v, accS[i * 8 + j]);
                    } else if (grp == 1) {
                        accA[i * 8 + j] = fmaf(gAs[r * 8 + 4 + e],  v, accA[i * 8 + j]);
                        accS[i * 8 + j] = fmaf(gSs[r * 12 + 4 + e], v, accS[i * 8 + j]);
                        accB[i * 8 + j] = fmaf(gBs[r * 8 + 4 + e],  v, accB[i * 8 + j]);
                    } else {
                        accS[i * 8 + j] = fmaf(gSs[r * 12 + 8 + e], v, accS[i * 8 + j]);
                        accB[i * 8 + j] = fmaf(gBs[r * 8 + e],      v, accB[i * 8 + j]);
                    }
                }
            }
        }
    }

    #pragma unroll
    for (int i = 0; i < 4; i++) {
        size_t r = (size_t)(b0 + r0 + i);
        #pragma unroll
        for (int j = 0; j < 8; j++) {
            size_t c = colb + j;
            out[r * DDIM + c]              = accA[i * 8 + j];
            out[(size_t)BD + r * DDIM + c] = accS[i * 8 + j];
            out[2ull * BD + r * DDIM + c]  = accB[i * 8 + j];
        }
    }
}

// ---------------------------------------------------------------------------
extern "C" void kernel_launch(void* const* d_in, const int* in_sizes, int n_in,
                              void* d_out, int out_size)
{
    const float* xA  = (const float*)d_in[0];
    const float* xS  = (const float*)d_in[1];
    const float* xB  = (const float*)d_in[2];
    const float* W1A = (const float*)d_in[3];
    const float* b1A = (const float*)d_in[4];
    const float* W2A = (const float*)d_in[5];
    const float* b2A = (const float*)d_in[6];
    const float* W1S = (const float*)d_in[7];
    const float* b1S = (const float*)d_in[8];
    const float* W2S = (const float*)d_in[9];
    const float* b2S = (const float*)d_in[10];
    const float* W1B = (const float*)d_in[11];
    const float* b1B = (const float*)d_in[12];
    const float* W2B = (const float*)d_in[13];
    const float* b2B = (const float*)d_in[14];
    const float* WgA = (const float*)d_in[15];
    const float* bgA = (const float*)d_in[16];
    const float* WgB = (const float*)d_in[17];
    const float* bgB = (const float*)d_in[18];
    const float* WgS = (const float*)d_in[19];
    const float* bgS = (const float*)d_in[20];
    float* out = (float*)d_out;

    static int cfg_done = 0;
    cudaFuncSetAttribute(xsplit_gates_kernel, cudaFuncAttributeMaxDynamicSharedMemorySize, 12 * 1024 * 4);
    cudaFuncSetAttribute(phase1_mma_kernel,   cudaFuncAttributeMaxDynamicSharedMemorySize, P1_SMEM);
    cudaFuncSetAttribute(phase2_kernel,       cudaFuncAttributeMaxDynamicSharedMemorySize, P2_SMEM);
    (void)cfg_done;

    wsplit_kernel<<<3072, 256>>>(W1A, W1S, W1B);
    xsplit_gates_kernel<<<dim3(2048, 3), 256, 12 * 1024 * 4>>>(xA, xS, xB, WgA, WgS, WgB, bgA, bgS, bgB);
    phase1_mma_kernel<<<dim3(2, 128, 3), 256, P1_SMEM>>>(b1A, b1S, b1B);
    phase2_kernel<<<BSZ / 32, 256, P2_SMEM>>>(W2A, b2A, W2S, b2S, W2B, b2B, out);
}

// round 8
// speedup vs baseline: 2.0828x; 1.2309x over previous
#include <cuda_runtime.h>
#include <cuda_bf16.h>
#include <cstdint>
#include <cstddef>
#include <math.h>

// Problem constants
#define BSZ   16384
#define FDIM  1024
#define HDIM  64
#define DDIM  256
#define NEXP  4
#define NH    256
#define BD    (BSZ * DDIM)

// ---------------------------------------------------------------------------
// Scratch (device globals — no allocation allowed)
// ---------------------------------------------------------------------------
__device__ float g_gA[BSZ * 8];
__device__ float g_gS[BSZ * 12];
__device__ float g_gB[BSZ * 8];

// bf16-split W1, transposed to [N=256][K=1024] rows
__device__ __align__(16) __nv_bfloat16 g_wh[3][256 * 1024];
__device__ __align__(16) __nv_bfloat16 g_wl[3][256 * 1024];
// bf16-split activations [B][1024]
__device__ __align__(16) __nv_bfloat16 g_xh[3][(size_t)BSZ * FDIM];
__device__ __align__(16) __nv_bfloat16 g_xl[3][(size_t)BSZ * FDIM];
// bf16-split hidden h [B][256] per group
__device__ __align__(16) __nv_bfloat16 g_hh[3][(size_t)BSZ * NH];
__device__ __align__(16) __nv_bfloat16 g_hl[3][(size_t)BSZ * NH];
// bf16-split W2 transposed: [z][e][D=256 rows][H=64 cols]
__device__ __align__(16) __nv_bfloat16 g_w2h[12][256 * 64];
__device__ __align__(16) __nv_bfloat16 g_w2l[12][256 * 64];

// ---------------------------------------------------------------------------
// Helpers
// ---------------------------------------------------------------------------
__device__ __forceinline__ uint32_t smem_u32(const void* p) {
    uint32_t a;
    asm("{ .reg .u64 t; cvta.to.shared.u64 t, %1; cvt.u32.u64 %0, t; }" : "=r"(a) : "l"(p));
    return a;
}
__device__ __forceinline__ void cp16(uint32_t dst, const void* src) {
    asm volatile("cp.async.cg.shared.global [%0], [%1], 16;" :: "r"(dst), "l"(src));
}
__device__ __forceinline__ void cp_commit() { asm volatile("cp.async.commit_group;" ::: "memory"); }
template <int N>
__device__ __forceinline__ void cp_wait() { asm volatile("cp.async.wait_group %0;" :: "n"(N) : "memory"); }

__device__ __forceinline__ void ldsm4(uint32_t* r, uint32_t addr) {
    asm volatile("ldmatrix.sync.aligned.m8n8.x4.shared.b16 {%0,%1,%2,%3}, [%4];"
                 : "=r"(r[0]), "=r"(r[1]), "=r"(r[2]), "=r"(r[3]) : "r"(addr));
}
__device__ __forceinline__ void mma16816(float* d, const uint32_t* a, const uint32_t* b) {
    asm volatile(
        "mma.sync.aligned.m16n8k16.row.col.f32.bf16.bf16.f32 "
        "{%0,%1,%2,%3}, {%4,%5,%6,%7}, {%8,%9}, {%0,%1,%2,%3};"
        : "+f"(d[0]), "+f"(d[1]), "+f"(d[2]), "+f"(d[3])
        : "r"(a[0]), "r"(a[1]), "r"(a[2]), "r"(a[3]), "r"(b[0]), "r"(b[1]));
}
__device__ __forceinline__ uint32_t packbf(float x, float y) {
    __nv_bfloat16 hx = __float2bfloat16(x);
    __nv_bfloat16 hy = __float2bfloat16(y);
    return ((uint32_t)__bfloat16_as_ushort(hy) << 16) | __bfloat16_as_ushort(hx);
}
__device__ __forceinline__ void split2(float x, float y, uint32_t& h, uint32_t& l) {
    h = packbf(x, y);
    float rx = x - __bfloat162float(__ushort_as_bfloat16((uint16_t)(h & 0xffff)));
    float ry = y - __bfloat162float(__ushort_as_bfloat16((uint16_t)(h >> 16)));
    l = packbf(rx, ry);
}

// ---------------------------------------------------------------------------
// wsplit: W1 [E,F,H] -> transposed [256][1024] hi/lo bf16
// ---------------------------------------------------------------------------
__global__ __launch_bounds__(256) void wsplit_kernel(
    const float* __restrict__ W1A, const float* __restrict__ W1S, const float* __restrict__ W1B)
{
    int id = blockIdx.x * 256 + threadIdx.x;
    int z = id >> 18;
    int r = id & 262143;
    int c = r >> 10, f = r & 1023;
    const float* W = (z == 0) ? W1A : (z == 1) ? W1S : W1B;
    float v = W[(size_t)(c >> 6) * 65536 + f * 64 + (c & 63)];
    __nv_bfloat16 h = __float2bfloat16(v);
    g_wh[z][c * 1024 + f] = h;
    g_wl[z][c * 1024 + f] = __float2bfloat16(v - __bfloat162float(h));
}

// w2split: W2 [E,H,D] -> [z*4+e][D=256 rows][H=64 cols] hi/lo bf16
__global__ __launch_bounds__(256) void w2split_kernel(
    const float* __restrict__ W2A, const float* __restrict__ W2S, const float* __restrict__ W2B)
{
    int id = blockIdx.x * 256 + threadIdx.x;  // 0..196607
    int z = id >> 16;
    int rem = id & 65535;
    int e = rem >> 14;
    int rem2 = rem & 16383;
    int hcol = rem2 >> 8;
    int d = rem2 & 255;
    const float* W = (z == 0) ? W2A : (z == 1) ? W2S : W2B;
    float v = W[e * 16384 + hcol * 256 + d];
    __nv_bfloat16 h = __float2bfloat16(v);
    g_w2h[z * 4 + e][d * 64 + hcol] = h;
    g_w2l[z * 4 + e][d * 64 + hcol] = __float2bfloat16(v - __bfloat162float(h));
}

// ---------------------------------------------------------------------------
// xsplit_gates: stream x once; emit xh/xl bf16 and gate softmax.
// ---------------------------------------------------------------------------
template <int G>
__device__ __forceinline__ void xsg_row(
    const float* __restrict__ xrow, __nv_bfloat16* __restrict__ hrow,
    __nv_bfloat16* __restrict__ lrow, const float* __restrict__ wT,
    const float* __restrict__ bg, float* __restrict__ gout, int lane)
{
    float acc[G];
    #pragma unroll
    for (int g = 0; g < G; g++) acc[g] = 0.f;

    #pragma unroll
    for (int j = 0; j < 8; j++) {
        int f0 = j * 128 + lane * 4;
        float4 xv = *(const float4*)(xrow + f0);
        uint32_t h0, h1, l0, l1;
        split2(xv.x, xv.y, h0, l0);
        split2(xv.z, xv.w, h1, l1);
        *(uint2*)(hrow + f0) = make_uint2(h0, h1);
        *(uint2*)(lrow + f0) = make_uint2(l0, l1);
        #pragma unroll
        for (int g = 0; g < G; g++) {
            float4 wv = *(const float4*)(wT + g * 1024 + f0);
            acc[g] += xv.x * wv.x + xv.y * wv.y + xv.z * wv.z + xv.w * wv.w;
        }
    }
    #pragma unroll
    for (int g = 0; g < G; g++) {
        #pragma unroll
        for (int o = 16; o > 0; o >>= 1) acc[g] += __shfl_xor_sync(0xffffffffu, acc[g], o);
    }
    if (lane == 0) {
        float l[G], m = -1e30f, s = 0.f;
        #pragma unroll
        for (int g = 0; g < G; g++) { l[g] = acc[g] + __ldg(&bg[g]); m = fmaxf(m, l[g]); }
        #pragma unroll
        for (int g = 0; g < G; g++) { l[g] = expf(l[g] - m); s += l[g]; }
        float inv = 1.f / s;
        #pragma unroll
        for (int g = 0; g < G; g++) gout[g] = l[g] * inv;
    }
}

__global__ __launch_bounds__(256) void xsplit_gates_kernel(
    const float* __restrict__ xA, const float* __restrict__ xS, const float* __restrict__ xB,
    const float* __restrict__ WgA, const float* __restrict__ WgS, const float* __restrict__ WgB,
    const float* __restrict__ bgA, const float* __restrict__ bgS, const float* __restrict__ bgB)
{
    extern __shared__ float wT[];
    int tid = threadIdx.x;
    int z = blockIdx.y;
    int G = (z == 1) ? 12 : 8;
    const float* X  = (z == 0) ? xA  : (z == 1) ? xS  : xB;
    const float* Wg = (z == 0) ? WgA : (z == 1) ? WgS : WgB;
    const float* bg = (z == 0) ? bgA : (z == 1) ? bgS : bgB;

    for (int i = tid; i < G * 1024; i += 256) {
        int f = i / G, g = i - f * G;
        wT[g * 1024 + f] = Wg[i];
    }
    __syncthreads();

    int wid = tid >> 5, lane = tid & 31;
    int row = blockIdx.x * 8 + wid;
    const float* xrow = X + (size_t)row * FDIM;
    __nv_bfloat16* hrow = g_xh[z] + (size_t)row * FDIM;
    __nv_bfloat16* lrow = g_xl[z] + (size_t)row * FDIM;

    if (z == 0)      xsg_row<8 >(xrow, hrow, lrow, wT, bg, g_gA + row * 8,  lane);
    else if (z == 1) xsg_row<12>(xrow, hrow, lrow, wT, bg, g_gS + row * 12, lane);
    else             xsg_row<8 >(xrow, hrow, lrow, wT, bg, g_gB + row * 8,  lane);
}

// ---------------------------------------------------------------------------
// Phase 1: bf16-split GEMM via mma.sync m16n8k16.
// CTA tile M=128, N=128, K-chunk=64. Epilogue writes bf16-split h.
// ---------------------------------------------------------------------------
#define P1_STAGE 65536
#define P1_SMEM  (2 * P1_STAGE)

__global__ __launch_bounds__(256) void phase1_mma_kernel(
    const float* __restrict__ b1A, const float* __restrict__ b1S, const float* __restrict__ b1B)
{
    extern __shared__ char smem[];
    uint32_t sb = smem_u32(smem);

    int tid  = threadIdx.x;
    int w    = tid >> 5;
    int lane = tid & 31;
    int wm   = w & 3;
    int wn   = w >> 2;
    int z    = blockIdx.z;
    int m0   = blockIdx.y * 128;
    int n0   = blockIdx.x * 128;

    const __nv_bfloat16* Xh = g_xh[z];
    const __nv_bfloat16* Xl = g_xl[z];
    const __nv_bfloat16* Wh = g_wh[z];
    const __nv_bfloat16* Wl = g_wl[z];
    const float* b1 = (z == 0) ? b1A : (z == 1) ? b1S : b1B;

    int trow[16], tsub[16], tpart[16];
    #pragma unroll
    for (int i = 0; i < 16; i++) {
        int task = i * 256 + tid;
        tpart[i] = task >> 10;
        int idx = task & 1023;
        trow[i] = idx >> 3;
        tsub[i] = idx & 7;
    }

    auto load_stage = [&](int s, int k0) {
        uint32_t base = sb + (uint32_t)s * P1_STAGE;
        #pragma unroll
        for (int i = 0; i < 16; i++) {
            int part = tpart[i], row = trow[i], sub = tsub[i];
            uint32_t dst = base + (uint32_t)part * 16384 + (uint32_t)(row * 128) +
                           (uint32_t)(((sub ^ (row & 7)) & 7) << 4);
            const __nv_bfloat16* src;
            if (part == 0)      src = Xh + (size_t)(m0 + row) * FDIM + k0 + sub * 8;
            else if (part == 1) src = Xl + (size_t)(m0 + row) * FDIM + k0 + sub * 8;
            else if (part == 2) src = Wh + (size_t)(n0 + row) * FDIM + k0 + sub * 8;
            else                src = Wl + (size_t)(n0 + row) * FDIM + k0 + sub * 8;
            cp16(dst, src);
        }
        cp_commit();
    };

    float D[2][8][4];
    #pragma unroll
    for (int mf = 0; mf < 2; mf++)
        #pragma unroll
        for (int nf = 0; nf < 8; nf++)
            #pragma unroll
            for (int k = 0; k < 4; k++) D[mf][nf][k] = 0.f;

    int q  = lane >> 3;
    int rr = lane & 7;

    load_stage(0, 0);

    for (int kc = 0; kc < 16; kc++) {
        int s = kc & 1;
        if (kc + 1 < 16) load_stage(s ^ 1, (kc + 1) * 64);
        if (kc + 1 < 16) cp_wait<1>(); else cp_wait<0>();
        __syncthreads();

        uint32_t sA  = sb + (uint32_t)s * P1_STAGE;
        uint32_t sAl = sA + 16384;
        uint32_t sBh = sA + 32768;
        uint32_t sBl = sA + 49152;

        #pragma unroll
        for (int kk = 0; kk < 4; kk++) {
            uint32_t Bh_[16], Bl_[16];
            #pragma unroll
            for (int bg = 0; bg < 4; bg++) {
                int rowb = wn * 64 + (bg * 2 + q / 2) * 8 + rr;
                int ch = kk * 2 + (q & 1);
                uint32_t off = (uint32_t)(rowb * 128 + ((ch ^ (rowb & 7)) << 4));
                ldsm4(&Bh_[bg * 4], sBh + off);
                ldsm4(&Bl_[bg * 4], sBl + off);
            }
            uint32_t Af_[2][4];
            #pragma unroll
            for (int mf = 0; mf < 2; mf++) {
                int rowa = wm * 32 + mf * 16 + (q & 1) * 8 + rr;
                int ch = kk * 2 + (q >> 1);
                uint32_t off = (uint32_t)(rowa * 128 + ((ch ^ (rowa & 7)) << 4));
                ldsm4(Af_[mf], sA + off);
            }
            #pragma unroll
            for (int mf = 0; mf < 2; mf++)
                #pragma unroll
                for (int nf = 0; nf < 8; nf++) {
                    mma16816(D[mf][nf], Af_[mf], &Bh_[nf * 2]);
                    mma16816(D[mf][nf], Af_[mf], &Bl_[nf * 2]);
                }
            #pragma unroll
            for (int mf = 0; mf < 2; mf++) {
                int rowa = wm * 32 + mf * 16 + (q & 1) * 8 + rr;
                int ch = kk * 2 + (q >> 1);
                uint32_t off = (uint32_t)(rowa * 128 + ((ch ^ (rowa & 7)) << 4));
                ldsm4(Af_[mf], sAl + off);
            }
            #pragma unroll
            for (int mf = 0; mf < 2; mf++)
                #pragma unroll
                for (int nf = 0; nf < 8; nf++)
                    mma16816(D[mf][nf], Af_[mf], &Bh_[nf * 2]);
        }
        __syncthreads();
    }

    // Epilogue: bias + relu -> bf16-split h
    __nv_bfloat16* Hh = g_hh[z];
    __nv_bfloat16* Hl = g_hl[z];
    #pragma unroll
    for (int nf = 0; nf < 8; nf++) {
        int col = n0 + wn * 64 + nf * 8 + (lane & 3) * 2;
        float bias0 = __ldg(&b1[col]);
        float bias1 = __ldg(&b1[col + 1]);
        #pragma unroll
        for (int mf = 0; mf < 2; mf++) {
            int row0 = m0 + wm * 32 + mf * 16 + (lane >> 2);
            float v00 = fmaxf(D[mf][nf][0] + bias0, 0.f);
            float v01 = fmaxf(D[mf][nf][1] + bias1, 0.f);
            float v10 = fmaxf(D[mf][nf][2] + bias0, 0.f);
            float v11 = fmaxf(D[mf][nf][3] + bias1, 0.f);
            uint32_t h0, l0, h1, l1;
            split2(v00, v01, h0, l0);
            split2(v10, v11, h1, l1);
            *(uint32_t*)(Hh + (size_t)row0 * NH + col)       = h0;
            *(uint32_t*)(Hl + (size_t)row0 * NH + col)       = l0;
            *(uint32_t*)(Hh + (size_t)(row0 + 8) * NH + col) = h1;
            *(uint32_t*)(Hl + (size_t)(row0 + 8) * NH + col) = l1;
        }
    }
}

// ---------------------------------------------------------------------------
// Phase 2: bf16-split mma.sync over experts with fused gate-weighted combine.
// grid = (BSZ/64, 3 outputs). Block 256 = 8 warps (2m x 4n), warp tile 32x64.
// Per expert: stage {H[64][64], W2T[256][64], b2[256]} hi/lo, double-buffered.
// out[frag] += gate[row] * relu(y[frag] + b2[col]); expert order == gate col.
// ---------------------------------------------------------------------------
#define SG_HH  0
#define SG_HL  8192
#define SG_WH  16384
#define SG_WL  49152
#define SG_B2  81920
#define STG2   82944
#define GS_OFF (2 * STG2)
#define P2_SMEM (GS_OFF + 64 * 12 * 4)   // 168960

__global__ __launch_bounds__(256, 1) void phase2_mma_kernel(
    const float* __restrict__ b2A, const float* __restrict__ b2S, const float* __restrict__ b2B,
    float* __restrict__ out)
{
    extern __shared__ char smem[];
    uint32_t sb = smem_u32(smem);
    float* gs = (float*)(smem + GS_OFF);

    int tid  = threadIdx.x;
    int w    = tid >> 5;
    int lane = tid & 31;
    int wm   = w >> 2;        // 0..1 (m-tiles of 32)
    int wn   = w & 3;         // 0..3 (n-tiles of 64)
    int o    = blockIdx.y;    // output: 0=A, 1=S, 2=B
    int m0   = blockIdx.x * 64;
    int Ecnt = (o == 1) ? 12 : 8;

    // gate staging: gs[64][12]
    {
        int G = (o == 1) ? 12 : 8;
        const float* gsrc = (o == 0) ? g_gA : (o == 1) ? g_gS : g_gB;
        for (int t = tid; t < 64 * 12; t += 256) {
            int r = t / 12, c = t - r * 12;
            if (c < G) gs[t] = gsrc[(size_t)(m0 + r) * G + c];
        }
    }

    // expert (z, e) schedule; expert index ei == gate column
    auto z_of = [&](int ei) -> int {
        if (o == 0) return ei < 4 ? 0 : 1;
        if (o == 1) return ei >> 2;
        return ei < 4 ? 2 : 1;
    };

    auto load_stage = [&](int s, int ei) {
        int z = z_of(ei);
        int e = ei & 3;
        const __nv_bfloat16* Hh = g_hh[z];
        const __nv_bfloat16* Hl = g_hl[z];
        const __nv_bfloat16* Wh = g_w2h[z * 4 + e];
        const __nv_bfloat16* Wl = g_w2l[z * 4 + e];
        const float* b2 = ((z == 0) ? b2A : (z == 1) ? b2S : b2B) + e * DDIM;
        uint32_t base = sb + (uint32_t)s * STG2;
        for (int i = tid; i < 5184; i += 256) {
            if (i < 1024) {
                int part = i >> 9;        // 0=Hh 1=Hl
                int idx = i & 511;
                int row = idx >> 3, sub = idx & 7;
                uint32_t dst = base + (part ? SG_HL : SG_HH) + (uint32_t)(row * 128) +
                               (uint32_t)(((sub ^ (row & 7)) & 7) << 4);
                const __nv_bfloat16* src = (part ? Hl : Hh) +
                    (size_t)(m0 + row) * NH + e * 64 + sub * 8;
                cp16(dst, src);
            } else if (i < 5120) {
                int j = i - 1024;
                int part = j >> 11;       // 0=Wh 1=Wl
                int idx = j & 2047;
                int row = idx >> 3, sub = idx & 7;
                uint32_t dst = base + (part ? SG_WL : SG_WH) + (uint32_t)(row * 128) +
                               (uint32_t)(((sub ^ (row & 7)) & 7) << 4);
                const __nv_bfloat16* src = (part ? Wl : Wh) + row * 64 + sub * 8;
                cp16(dst, src);
            } else {
                int idx = i - 5120;       // 64 chunks of b2
                cp16(base + SG_B2 + (uint32_t)(idx * 16), b2 + idx * 4);
            }
        }
        cp_commit();
    };

    float acc[2][8][4];
    #pragma unroll
    for (int mf = 0; mf < 2; mf++)
        #pragma unroll
        for (int nf = 0; nf < 8; nf++)
            #pragma unroll
            for (int k = 0; k < 4; k++) acc[mf][nf][k] = 0.f;

    int q  = lane >> 3;
    int rr = lane & 7;

    load_stage(0, 0);

    for (int ei = 0; ei < Ecnt; ei++) {
        int s = ei & 1;
        if (ei + 1 < Ecnt) { load_stage(s ^ 1, ei + 1); cp_wait<1>(); }
        else               { cp_wait<0>(); }
        __syncthreads();

        uint32_t sHh = sb + (uint32_t)s * STG2 + SG_HH;
        uint32_t sHl = sHh + 8192;
        uint32_t sWh = sb + (uint32_t)s * STG2 + SG_WH;
        uint32_t sWl = sb + (uint32_t)s * STG2 + SG_WL;
        const float* b2s = (const float*)(smem + s * STG2 + SG_B2);

        float y[2][8][4];
        #pragma unroll
        for (int mf = 0; mf < 2; mf++)
            #pragma unroll
            for (int nf = 0; nf < 8; nf++)
                #pragma unroll
                for (int k = 0; k < 4; k++) y[mf][nf][k] = 0.f;

        #pragma unroll
        for (int kk = 0; kk < 4; kk++) {
            uint32_t Bh_[16], Bl_[16];
            #pragma unroll
            for (int bg = 0; bg < 4; bg++) {
                int rowb = wn * 64 + (bg * 2 + q / 2) * 8 + rr;
                int ch = kk * 2 + (q & 1);
                uint32_t off = (uint32_t)(rowb * 128 + ((ch ^ (rowb & 7)) << 4));
                ldsm4(&Bh_[bg * 4], sWh + off);
                ldsm4(&Bl_[bg * 4], sWl + off);
            }
            uint32_t Af_[2][4];
            #pragma unroll
            for (int mf = 0; mf < 2; mf++) {
                int rowa = wm * 32 + mf * 16 + (q & 1) * 8 + rr;
                int ch = kk * 2 + (q >> 1);
                uint32_t off = (uint32_t)(rowa * 128 + ((ch ^ (rowa & 7)) << 4));
                ldsm4(Af_[mf], sHh + off);
            }
            #pragma unroll
            for (int mf = 0; mf < 2; mf++)
                #pragma unroll
                for (int nf = 0; nf < 8; nf++) {
                    mma16816(y[mf][nf], Af_[mf], &Bh_[nf * 2]);
                    mma16816(y[mf][nf], Af_[mf], &Bl_[nf * 2]);
                }
            #pragma unroll
            for (int mf = 0; mf < 2; mf++) {
                int rowa = wm * 32 + mf * 16 + (q & 1) * 8 + rr;
                int ch = kk * 2 + (q >> 1);
                uint32_t off = (uint32_t)(rowa * 128 + ((ch ^ (rowa & 7)) << 4));
                ldsm4(Af_[mf], sHl + off);
            }
            #pragma unroll
            for (int mf = 0; mf < 2; mf++)
                #pragma unroll
                for (int nf = 0; nf < 8; nf++)
                    mma16816(y[mf][nf], Af_[mf], &Bh_[nf * 2]);
        }

        // gate-weighted relu accumulation (fragment layout)
        #pragma unroll
        for (int mf = 0; mf < 2; mf++) {
            int r0 = wm * 32 + mf * 16 + (lane >> 2);
            float g0 = gs[r0 * 12 + ei];
            float g1 = gs[(r0 + 8) * 12 + ei];
            #pragma unroll
            for (int nf = 0; nf < 8; nf++) {
                int c0 = wn * 64 + nf * 8 + (lane & 3) * 2;
                float bb0 = b2s[c0];
                float bb1 = b2s[c0 + 1];
                acc[mf][nf][0] = fmaf(g0, fmaxf(y[mf][nf][0] + bb0, 0.f), acc[mf][nf][0]);
                acc[mf][nf][1] = fmaf(g0, fmaxf(y[mf][nf][1] + bb1, 0.f), acc[mf][nf][1]);
                acc[mf][nf][2] = fmaf(g1, fmaxf(y[mf][nf][2] + bb0, 0.f), acc[mf][nf][2]);
                acc[mf][nf][3] = fmaf(g1, fmaxf(y[mf][nf][3] + bb1, 0.f), acc[mf][nf][3]);
            }
        }
        __syncthreads();
    }

    // write output
    float* obase = out + (size_t)o * BD;
    #pragma unroll
    for (int mf = 0; mf < 2; mf++) {
        int r0 = m0 + wm * 32 + mf * 16 + (lane >> 2);
        #pragma unroll
        for (int nf = 0; nf < 8; nf++) {
            int c0 = wn * 64 + nf * 8 + (lane & 3) * 2;
            *(float2*)(obase + (size_t)r0 * DDIM + c0)       = make_float2(acc[mf][nf][0], acc[mf][nf][1]);
            *(float2*)(obase + (size_t)(r0 + 8) * DDIM + c0) = make_float2(acc[mf][nf][2], acc[mf][nf][3]);
        }
    }
}

// ---------------------------------------------------------------------------
extern "C" void kernel_launch(void* const* d_in, const int* in_sizes, int n_in,
                              void* d_out, int out_size)
{
    const float* xA  = (const float*)d_in[0];
    const float* xS  = (const float*)d_in[1];
    const float* xB  = (const float*)d_in[2];
    const float* W1A = (const float*)d_in[3];
    const float* b1A = (const float*)d_in[4];
    const float* W2A = (const float*)d_in[5];
    const float* b2A = (const float*)d_in[6];
    const float* W1S = (const float*)d_in[7];
    const float* b1S = (const float*)d_in[8];
    const float* W2S = (const float*)d_in[9];
    const float* b2S = (const float*)d_in[10];
    const float* W1B = (const float*)d_in[11];
    const float* b1B = (const float*)d_in[12];
    const float* W2B = (const float*)d_in[13];
    const float* b2B = (const float*)d_in[14];
    const float* WgA = (const float*)d_in[15];
    const float* bgA = (const float*)d_in[16];
    const float* WgB = (const float*)d_in[17];
    const float* bgB = (const float*)d_in[18];
    const float* WgS = (const float*)d_in[19];
    const float* bgS = (const float*)d_in[20];
    float* out = (float*)d_out;

    cudaFuncSetAttribute(xsplit_gates_kernel, cudaFuncAttributeMaxDynamicSharedMemorySize, 12 * 1024 * 4);
    cudaFuncSetAttribute(phase1_mma_kernel,   cudaFuncAttributeMaxDynamicSharedMemorySize, P1_SMEM);
    cudaFuncSetAttribute(phase2_mma_kernel,   cudaFuncAttributeMaxDynamicSharedMemorySize, P2_SMEM);

    wsplit_kernel<<<3072, 256>>>(W1A, W1S, W1B);
    w2split_kernel<<<768, 256>>>(W2A, W2S, W2B);
    xsplit_gates_kernel<<<dim3(2048, 3), 256, 12 * 1024 * 4>>>(xA, xS, xB, WgA, WgS, WgB, bgA, bgS, bgB);
    phase1_mma_kernel<<<dim3(2, 128, 3), 256, P1_SMEM>>>(b1A, b1S, b1B);
    phase2_mma_kernel<<<dim3(BSZ / 64, 3), 256, P2_SMEM>>>(b2A, b2S, b2B, out);
}

// round 11
// speedup vs baseline: 2.2655x; 1.0877x over previous
#include <cuda_runtime.h>
#include <cuda_bf16.h>
#include <cstdint>
#include <cstddef>
#include <math.h>

// Problem constants
#define BSZ   16384
#define FDIM  1024
#define HDIM  64
#define DDIM  256
#define NEXP  4
#define NH    256
#define BD    (BSZ * DDIM)

// ---------------------------------------------------------------------------
// Scratch (device globals — no allocation allowed)
// ---------------------------------------------------------------------------
__device__ float g_gA[BSZ * 8];
__device__ float g_gS[BSZ * 12];
__device__ float g_gB[BSZ * 8];

// bf16-split W1, transposed to [N=256][K=1024] rows
__device__ __align__(16) __nv_bfloat16 g_wh[3][256 * 1024];
__device__ __align__(16) __nv_bfloat16 g_wl[3][256 * 1024];
// bf16-split activations [B][1024]
__device__ __align__(16) __nv_bfloat16 g_xh[3][(size_t)BSZ * FDIM];
__device__ __align__(16) __nv_bfloat16 g_xl[3][(size_t)BSZ * FDIM];
// bf16-split hidden h [B][256] per group
__device__ __align__(16) __nv_bfloat16 g_hh[3][(size_t)BSZ * NH];
__device__ __align__(16) __nv_bfloat16 g_hl[3][(size_t)BSZ * NH];
// bf16-split W2 transposed: [z][e][D=256 rows][H=64 cols]
__device__ __align__(16) __nv_bfloat16 g_w2h[12][256 * 64];
__device__ __align__(16) __nv_bfloat16 g_w2l[12][256 * 64];

// ---------------------------------------------------------------------------
// Helpers
// ---------------------------------------------------------------------------
__device__ __forceinline__ uint32_t smem_u32(const void* p) {
    uint32_t a;
    asm("{ .reg .u64 t; cvta.to.shared.u64 t, %1; cvt.u32.u64 %0, t; }" : "=r"(a) : "l"(p));
    return a;
}
__device__ __forceinline__ void cp16(uint32_t dst, const void* src) {
    asm volatile("cp.async.cg.shared.global [%0], [%1], 16;" :: "r"(dst), "l"(src));
}
__device__ __forceinline__ void cp_commit() { asm volatile("cp.async.commit_group;" ::: "memory"); }
template <int N>
__device__ __forceinline__ void cp_wait() { asm volatile("cp.async.wait_group %0;" :: "n"(N) : "memory"); }

__device__ __forceinline__ void ldsm4(uint32_t* r, uint32_t addr) {
    asm volatile("ldmatrix.sync.aligned.m8n8.x4.shared.b16 {%0,%1,%2,%3}, [%4];"
                 : "=r"(r[0]), "=r"(r[1]), "=r"(r[2]), "=r"(r[3]) : "r"(addr));
}
__device__ __forceinline__ void mma16816(float* d, const uint32_t* a, const uint32_t* b) {
    asm volatile(
        "mma.sync.aligned.m16n8k16.row.col.f32.bf16.bf16.f32 "
        "{%0,%1,%2,%3}, {%4,%5,%6,%7}, {%8,%9}, {%0,%1,%2,%3};"
        : "+f"(d[0]), "+f"(d[1]), "+f"(d[2]), "+f"(d[3])
        : "r"(a[0]), "r"(a[1]), "r"(a[2]), "r"(a[3]), "r"(b[0]), "r"(b[1]));
}
__device__ __forceinline__ uint32_t packbf(float x, float y) {
    __nv_bfloat16 hx = __float2bfloat16(x);
    __nv_bfloat16 hy = __float2bfloat16(y);
    return ((uint32_t)__bfloat16_as_ushort(hy) << 16) | __bfloat16_as_ushort(hx);
}
__device__ __forceinline__ void split2(float x, float y, uint32_t& h, uint32_t& l) {
    h = packbf(x, y);
    float rx = x - __bfloat162float(__ushort_as_bfloat16((uint16_t)(h & 0xffff)));
    float ry = y - __bfloat162float(__ushort_as_bfloat16((uint16_t)(h >> 16)));
    l = packbf(rx, ry);
}

// ---------------------------------------------------------------------------
// wsplit: W1 [E,F,H] -> transposed [256][1024] hi/lo bf16
// ---------------------------------------------------------------------------
__global__ __launch_bounds__(256) void wsplit_kernel(
    const float* __restrict__ W1A, const float* __restrict__ W1S, const float* __restrict__ W1B)
{
    int id = blockIdx.x * 256 + threadIdx.x;
    int z = id >> 18;
    int r = id & 262143;
    int c = r >> 10, f = r & 1023;
    const float* W = (z == 0) ? W1A : (z == 1) ? W1S : W1B;
    float v = W[(size_t)(c >> 6) * 65536 + f * 64 + (c & 63)];
    __nv_bfloat16 h = __float2bfloat16(v);
    g_wh[z][c * 1024 + f] = h;
    g_wl[z][c * 1024 + f] = __float2bfloat16(v - __bfloat162float(h));
}

// w2split: W2 [E,H,D] -> [z*4+e][D=256 rows][H=64 cols] hi/lo bf16
__global__ __launch_bounds__(256) void w2split_kernel(
    const float* __restrict__ W2A, const float* __restrict__ W2S, const float* __restrict__ W2B)
{
    int id = blockIdx.x * 256 + threadIdx.x;  // 0..196607
    int z = id >> 16;
    int rem = id & 65535;
    int e = rem >> 14;
    int rem2 = rem & 16383;
    int hcol = rem2 >> 8;
    int d = rem2 & 255;
    const float* W = (z == 0) ? W2A : (z == 1) ? W2S : W2B;
    float v = W[e * 16384 + hcol * 256 + d];
    __nv_bfloat16 h = __float2bfloat16(v);
    g_w2h[z * 4 + e][d * 64 + hcol] = h;
    g_w2l[z * 4 + e][d * 64 + hcol] = __float2bfloat16(v - __bfloat162float(h));
}

// ---------------------------------------------------------------------------
// xsplit_gates: stream x once; emit xh/xl bf16 and gate softmax.
// ---------------------------------------------------------------------------
template <int G>
__device__ __forceinline__ void xsg_row(
    const float* __restrict__ xrow, __nv_bfloat16* __restrict__ hrow,
    __nv_bfloat16* __restrict__ lrow, const float* __restrict__ wT,
    const float* __restrict__ bg, float* __restrict__ gout, int lane)
{
    float acc[G];
    #pragma unroll
    for (int g = 0; g < G; g++) acc[g] = 0.f;

    #pragma unroll
    for (int j = 0; j < 8; j++) {
        int f0 = j * 128 + lane * 4;
        float4 xv = *(const float4*)(xrow + f0);
        uint32_t h0, h1, l0, l1;
        split2(xv.x, xv.y, h0, l0);
        split2(xv.z, xv.w, h1, l1);
        *(uint2*)(hrow + f0) = make_uint2(h0, h1);
        *(uint2*)(lrow + f0) = make_uint2(l0, l1);
        #pragma unroll
        for (int g = 0; g < G; g++) {
            float4 wv = *(const float4*)(wT + g * 1024 + f0);
            acc[g] += xv.x * wv.x + xv.y * wv.y + xv.z * wv.z + xv.w * wv.w;
        }
    }
    #pragma unroll
    for (int g = 0; g < G; g++) {
        #pragma unroll
        for (int o = 16; o > 0; o >>= 1) acc[g] += __shfl_xor_sync(0xffffffffu, acc[g], o);
    }
    if (lane == 0) {
        float l[G], m = -1e30f, s = 0.f;
        #pragma unroll
        for (int g = 0; g < G; g++) { l[g] = acc[g] + __ldg(&bg[g]); m = fmaxf(m, l[g]); }
        #pragma unroll
        for (int g = 0; g < G; g++) { l[g] = expf(l[g] - m); s += l[g]; }
        float inv = 1.f / s;
        #pragma unroll
        for (int g = 0; g < G; g++) gout[g] = l[g] * inv;
    }
}

__global__ __launch_bounds__(256) void xsplit_gates_kernel(
    const float* __restrict__ xA, const float* __restrict__ xS, const float* __restrict__ xB,
    const float* __restrict__ WgA, const float* __restrict__ WgS, const float* __restrict__ WgB,
    const float* __restrict__ bgA, const float* __restrict__ bgS, const float* __restrict__ bgB)
{
    extern __shared__ float wT[];
    int tid = threadIdx.x;
    int z = blockIdx.y;
    int G = (z == 1) ? 12 : 8;
    const float* X  = (z == 0) ? xA  : (z == 1) ? xS  : xB;
    const float* Wg = (z == 0) ? WgA : (z == 1) ? WgS : WgB;
    const float* bg = (z == 0) ? bgA : (z == 1) ? bgS : bgB;

    for (int i = tid; i < G * 1024; i += 256) {
        int f = i / G, g = i - f * G;
        wT[g * 1024 + f] = Wg[i];
    }
    __syncthreads();

    int wid = tid >> 5, lane = tid & 31;
    int row = blockIdx.x * 8 + wid;
    const float* xrow = X + (size_t)row * FDIM;
    __nv_bfloat16* hrow = g_xh[z] + (size_t)row * FDIM;
    __nv_bfloat16* lrow = g_xl[z] + (size_t)row * FDIM;

    if (z == 0)      xsg_row<8 >(xrow, hrow, lrow, wT, bg, g_gA + row * 8,  lane);
    else if (z == 1) xsg_row<12>(xrow, hrow, lrow, wT, bg, g_gS + row * 12, lane);
    else             xsg_row<8 >(xrow, hrow, lrow, wT, bg, g_gB + row * 8,  lane);
}

// ---------------------------------------------------------------------------
// Phase 1: bf16-split GEMM via mma.sync m16n8k16.
// CTA tile M=128, N=128, K-chunk=32. hi/lo PACKED in one 128B smem row:
// chunks 0-3 = hi (k0..31), chunks 4-7 = lo (k0..31). Stage = A 16KB + B 16KB
// = 32KB; 2 stages = 64KB -> 2 CTAs/SM. grid = (2, 128, 3).
// ---------------------------------------------------------------------------
#define P1_STAGE 32768
#define P1_SMEM  (2 * P1_STAGE)

__global__ __launch_bounds__(256, 2) void phase1_mma_kernel(
    const float* __restrict__ b1A, const float* __restrict__ b1S, const float* __restrict__ b1B)
{
    extern __shared__ char smem[];
    uint32_t sb = smem_u32(smem);

    int tid  = threadIdx.x;
    int w    = tid >> 5;
    int lane = tid & 31;
    int wm   = w & 3;
    int wn   = w >> 2;
    int z    = blockIdx.z;
    int m0   = blockIdx.y * 128;
    int n0   = blockIdx.x * 128;

    const __nv_bfloat16* Xh = g_xh[z];
    const __nv_bfloat16* Xl = g_xl[z];
    const __nv_bfloat16* Wh = g_wh[z];
    const __nv_bfloat16* Wl = g_wl[z];
    const float* b1 = (z == 0) ? b1A : (z == 1) ? b1S : b1B;

    // 2048 16B-chunks per stage: part(A/B) = task>>10, row = (task&1023)>>3,
    // sub = task&7. sub 0-3 => hi data, sub 4-7 => lo data (same k window).
    int trow[8], tsub[8], tpart[8];
    #pragma unroll
    for (int i = 0; i < 8; i++) {
        int task = i * 256 + tid;
        tpart[i] = task >> 10;
        int idx = task & 1023;
        trow[i] = idx >> 3;
        tsub[i] = idx & 7;
    }

    auto load_stage = [&](int s, int k0) {
        uint32_t base = sb + (uint32_t)s * P1_STAGE;
        #pragma unroll
        for (int i = 0; i < 8; i++) {
            int part = tpart[i], row = trow[i], sub = tsub[i];
            uint32_t dst = base + (uint32_t)part * 16384 + (uint32_t)(row * 128) +
                           (uint32_t)(((sub ^ (row & 7)) & 7) << 4);
            const __nv_bfloat16* src;
            int kof = (sub & 3) * 8;
            if (part == 0) src = ((sub < 4) ? Xh : Xl) + (size_t)(m0 + row) * FDIM + k0 + kof;
            else           src = ((sub < 4) ? Wh : Wl) + (size_t)(n0 + row) * FDIM + k0 + kof;
            cp16(dst, src);
        }
        cp_commit();
    };

    float D[2][8][4];
    #pragma unroll
    for (int mf = 0; mf < 2; mf++)
        #pragma unroll
        for (int nf = 0; nf < 8; nf++)
            #pragma unroll
            for (int k = 0; k < 4; k++) D[mf][nf][k] = 0.f;

    int q  = lane >> 3;
    int rr = lane & 7;

    load_stage(0, 0);

    for (int kc = 0; kc < 32; kc++) {
        int s = kc & 1;
        if (kc + 1 < 32) { load_stage(s ^ 1, (kc + 1) * 32); cp_wait<1>(); }
        else             { cp_wait<0>(); }
        __syncthreads();

        uint32_t sA = sb + (uint32_t)s * P1_STAGE;
        uint32_t sB = sA + 16384;

        #pragma unroll
        for (int kk = 0; kk < 2; kk++) {
            uint32_t Bh_[16], Bl_[16];
            #pragma unroll
            for (int bg = 0; bg < 4; bg++) {
                int rowb = wn * 64 + (bg * 2 + q / 2) * 8 + rr;
                int ch = kk * 2 + (q & 1);
                ldsm4(&Bh_[bg * 4], sB + (uint32_t)(rowb * 128 + ((ch ^ (rowb & 7)) << 4)));
                ldsm4(&Bl_[bg * 4], sB + (uint32_t)(rowb * 128 + (((ch + 4) ^ (rowb & 7)) << 4)));
            }
            uint32_t Af_[2][4];
            #pragma unroll
            for (int mf = 0; mf < 2; mf++) {
                int rowa = wm * 32 + mf * 16 + (q & 1) * 8 + rr;
                int ch = kk * 2 + (q >> 1);
                ldsm4(Af_[mf], sA + (uint32_t)(rowa * 128 + ((ch ^ (rowa & 7)) << 4)));
            }
            #pragma unroll
            for (int mf = 0; mf < 2; mf++)
                #pragma unroll
                for (int nf = 0; nf < 8; nf++) {
                    mma16816(D[mf][nf], Af_[mf], &Bh_[nf * 2]);
                    mma16816(D[mf][nf], Af_[mf], &Bl_[nf * 2]);
                }
            #pragma unroll
            for (int mf = 0; mf < 2; mf++) {
                int rowa = wm * 32 + mf * 16 + (q & 1) * 8 + rr;
                int ch = kk * 2 + (q >> 1) + 4;
                ldsm4(Af_[mf], sA + (uint32_t)(rowa * 128 + ((ch ^ (rowa & 7)) << 4)));
            }
            #pragma unroll
            for (int mf = 0; mf < 2; mf++)
                #pragma unroll
                for (int nf = 0; nf < 8; nf++)
                    mma16816(D[mf][nf], Af_[mf], &Bh_[nf * 2]);
        }
        __syncthreads();
    }

    // Epilogue: bias + relu -> bf16-split h
    __nv_bfloat16* Hh = g_hh[z];
    __nv_bfloat16* Hl = g_hl[z];
    #pragma unroll
    for (int nf = 0; nf < 8; nf++) {
        int col = n0 + wn * 64 + nf * 8 + (lane & 3) * 2;
        float bias0 = __ldg(&b1[col]);
        float bias1 = __ldg(&b1[col + 1]);
        #pragma unroll
        for (int mf = 0; mf < 2; mf++) {
            int row0 = m0 + wm * 32 + mf * 16 + (lane >> 2);
            float v00 = fmaxf(D[mf][nf][0] + bias0, 0.f);
            float v01 = fmaxf(D[mf][nf][1] + bias1, 0.f);
            float v10 = fmaxf(D[mf][nf][2] + bias0, 0.f);
            float v11 = fmaxf(D[mf][nf][3] + bias1, 0.f);
            uint32_t h0, l0, h1, l1;
            split2(v00, v01, h0, l0);
            split2(v10, v11, h1, l1);
            *(uint32_t*)(Hh + (size_t)row0 * NH + col)       = h0;
            *(uint32_t*)(Hl + (size_t)row0 * NH + col)       = l0;
            *(uint32_t*)(Hh + (size_t)(row0 + 8) * NH + col) = h1;
            *(uint32_t*)(Hl + (size_t)(row0 + 8) * NH + col) = l1;
        }
    }
}

// ---------------------------------------------------------------------------
// Phase 2: bf16-split mma.sync over experts, fused gate-weighted combine.
// grid = (BSZ/64, 6): blockIdx.y = o*2 + nhalf; CTA covers 64 rows x 128 cols.
// 8 warps (2m x 4n), warp tile 32x32. Stage {H 16KB, W2T-half 32KB, b2 0.5KB},
// double-buffered ~= 99KB + gates -> 2 CTAs/SM.
// ---------------------------------------------------------------------------
#define SG_HH  0
#define SG_HL  8192
#define SG_WH  16384
#define SG_WL  32768
#define SG_B2  49152
#define STG2   49664
#define GS_OFF (2 * STG2)
#define P2_SMEM (GS_OFF + 64 * 12 * 4)   // 102400

__global__ __launch_bounds__(256, 2) void phase2_mma_kernel(
    const float* __restrict__ b2A, const float* __restrict__ b2S, const float* __restrict__ b2B,
    float* __restrict__ out)
{
    extern __shared__ char smem[];
    uint32_t sb = smem_u32(smem);
    float* gs = (float*)(smem + GS_OFF);

    int tid  = threadIdx.x;
    int w    = tid >> 5;
    int lane = tid & 31;
    int wm   = w >> 2;        // 0..1 (m-tiles of 32)
    int wn   = w & 3;         // 0..3 (n-tiles of 32)
    int o      = blockIdx.y >> 1;   // output: 0=A, 1=S, 2=B
    int nhalf  = blockIdx.y & 1;    // which 128-col half of D
    int m0   = blockIdx.x * 64;
    int Ecnt = (o == 1) ? 12 : 8;

    // gate staging: gs[64][12]
    {
        int G = (o == 1) ? 12 : 8;
        const float* gsrc = (o == 0) ? g_gA : (o == 1) ? g_gS : g_gB;
        for (int t = tid; t < 64 * 12; t += 256) {
            int r = t / 12, c = t - r * 12;
            if (c < G) gs[t] = gsrc[(size_t)(m0 + r) * G + c];
        }
    }

    auto z_of = [&](int ei) -> int {
        if (o == 0) return ei < 4 ? 0 : 1;
        if (o == 1) return ei >> 2;
        return ei < 4 ? 2 : 1;
    };

    auto load_stage = [&](int s, int ei) {
        int z = z_of(ei);
        int e = ei & 3;
        const __nv_bfloat16* Hh = g_hh[z];
        const __nv_bfloat16* Hl = g_hl[z];
        const __nv_bfloat16* Wh = g_w2h[z * 4 + e] + nhalf * 128 * 64;
        const __nv_bfloat16* Wl = g_w2l[z * 4 + e] + nhalf * 128 * 64;
        const float* b2 = ((z == 0) ? b2A : (z == 1) ? b2S : b2B) + e * DDIM + nhalf * 128;
        uint32_t base = sb + (uint32_t)s * STG2;
        for (int i = tid; i < 3104; i += 256) {
            if (i < 1024) {
                int part = i >> 9;        // 0=Hh 1=Hl
                int idx = i & 511;
                int row = idx >> 3, sub = idx & 7;
                uint32_t dst = base + (part ? SG_HL : SG_HH) + (uint32_t)(row * 128) +
                               (uint32_t)(((sub ^ (row & 7)) & 7) << 4);
                const __nv_bfloat16* src = (part ? Hl : Hh) +
                    (size_t)(m0 + row) * NH + e * 64 + sub * 8;
                cp16(dst, src);
            } else if (i < 3072) {
                int j = i - 1024;
                int part = j >> 10;       // 0=Wh 1=Wl
                int idx = j & 1023;
                int row = idx >> 3, sub = idx & 7;
                uint32_t dst = base + (part ? SG_WL : SG_WH) + (uint32_t)(row * 128) +
                               (uint32_t)(((sub ^ (row & 7)) & 7) << 4);
                const __nv_bfloat16* src = (part ? Wl : Wh) + row * 64 + sub * 8;
                cp16(dst, src);
            } else {
                int idx = i - 3072;       // 32 chunks of b2 (128 floats)
                cp16(base + SG_B2 + (uint32_t)(idx * 16), b2 + idx * 4);
            }
        }
        cp_commit();
    };

    float acc[2][4][4];
    #pragma unroll
    for (int mf = 0; mf < 2; mf++)
        #pragma unroll
        for (int nf = 0; nf < 4; nf++)
            #pragma unroll
            for (int k = 0; k < 4; k++) acc[mf][nf][k] = 0.f;

    int q  = lane >> 3;
    int rr = lane & 7;

    load_stage(0, 0);

    for (int ei = 0; ei < Ecnt; ei++) {
        int s = ei & 1;
        if (ei + 1 < Ecnt) { load_stage(s ^ 1, ei + 1); cp_wait<1>(); }
        else               { cp_wait<0>(); }
        __syncthreads();

        uint32_t sHh = sb + (uint32_t)s * STG2 + SG_HH;
        uint32_t sHl = sHh + 8192;
        uint32_t sWh = sb + (uint32_t)s * STG2 + SG_WH;
        uint32_t sWl = sb + (uint32_t)s * STG2 + SG_WL;
        const float* b2s = (const float*)(smem + s * STG2 + SG_B2);

        float y[2][4][4];
        #pragma unroll
        for (int mf = 0; mf < 2; mf++)
            #pragma unroll
            for (int nf = 0; nf < 4; nf++)
                #pragma unroll
                for (int k = 0; k < 4; k++) y[mf][nf][k] = 0.f;

        #pragma unroll
        for (int kk = 0; kk < 4; kk++) {
            uint32_t Bh_[8], Bl_[8];
            #pragma unroll
            for (int bg = 0; bg < 2; bg++) {
                int rowb = wn * 32 + (bg * 2 + q / 2) * 8 + rr;
                int ch = kk * 2 + (q & 1);
                uint32_t off = (uint32_t)(rowb * 128 + ((ch ^ (rowb & 7)) << 4));
                ldsm4(&Bh_[bg * 4], sWh + off);
                ldsm4(&Bl_[bg * 4], sWl + off);
            }
            uint32_t Af_[2][4];
            #pragma unroll
            for (int mf = 0; mf < 2; mf++) {
                int rowa = wm * 32 + mf * 16 + (q & 1) * 8 + rr;
                int ch = kk * 2 + (q >> 1);
                uint32_t off = (uint32_t)(rowa * 128 + ((ch ^ (rowa & 7)) << 4));
                ldsm4(Af_[mf], sHh + off);
            }
            #pragma unroll
            for (int mf = 0; mf < 2; mf++)
                #pragma unroll
                for (int nf = 0; nf < 4; nf++) {
                    mma16816(y[mf][nf], Af_[mf], &Bh_[nf * 2]);
                    mma16816(y[mf][nf], Af_[mf], &Bl_[nf * 2]);
                }
            #pragma unroll
            for (int mf = 0; mf < 2; mf++) {
                int rowa = wm * 32 + mf * 16 + (q & 1) * 8 + rr;
                int ch = kk * 2 + (q >> 1);
                uint32_t off = (uint32_t)(rowa * 128 + ((ch ^ (rowa & 7)) << 4));
                ldsm4(Af_[mf], sHl + off);
            }
            #pragma unroll
            for (int mf = 0; mf < 2; mf++)
                #pragma unroll
                for (int nf = 0; nf < 4; nf++)
                    mma16816(y[mf][nf], Af_[mf], &Bh_[nf * 2]);
        }

        // gate-weighted relu accumulation (fragment layout)
        #pragma unroll
        for (int mf = 0; mf < 2; mf++) {
            int r0 = wm * 32 + mf * 16 + (lane >> 2);
            float g0 = gs[r0 * 12 + ei];
            float g1 = gs[(r0 + 8) * 12 + ei];
            #pragma unroll
            for (int nf = 0; nf < 4; nf++) {
                int c0 = wn * 32 + nf * 8 + (lane & 3) * 2;
                float bb0 = b2s[c0];
                float bb1 = b2s[c0 + 1];
                acc[mf][nf][0] = fmaf(g0, fmaxf(y[mf][nf][0] + bb0, 0.f), acc[mf][nf][0]);
                acc[mf][nf][1] = fmaf(g0, fmaxf(y[mf][nf][1] + bb1, 0.f), acc[mf][nf][1]);
                acc[mf][nf][2] = fmaf(g1, fmaxf(y[mf][nf][2] + bb0, 0.f), acc[mf][nf][2]);
                acc[mf][nf][3] = fmaf(g1, fmaxf(y[mf][nf][3] + bb1, 0.f), acc[mf][nf][3]);
            }
        }
        __syncthreads();
    }

    // write output
    float* obase = out + (size_t)o * BD + nhalf * 128;
    #pragma unroll
    for (int mf = 0; mf < 2; mf++) {
        int r0 = m0 + wm * 32 + mf * 16 + (lane >> 2);
        #pragma unroll
        for (int nf = 0; nf < 4; nf++) {
            int c0 = wn * 32 + nf * 8 + (lane & 3) * 2;
            *(float2*)(obase + (size_t)r0 * DDIM + c0)       = make_float2(acc[mf][nf][0], acc[mf][nf][1]);
            *(float2*)(obase + (size_t)(r0 + 8) * DDIM + c0) = make_float2(acc[mf][nf][2], acc[mf][nf][3]);
        }
    }
}

// ---------------------------------------------------------------------------
extern "C" void kernel_launch(void* const* d_in, const int* in_sizes, int n_in,
                              void* d_out, int out_size)
{
    const float* xA  = (const float*)d_in[0];
    const float* xS  = (const float*)d_in[1];
    const float* xB  = (const float*)d_in[2];
    const float* W1A = (const float*)d_in[3];
    const float* b1A = (const float*)d_in[4];
    const float* W2A = (const float*)d_in[5];
    const float* b2A = (const float*)d_in[6];
    const float* W1S = (const float*)d_in[7];
    const float* b1S = (const float*)d_in[8];
    const float* W2S = (const float*)d_in[9];
    const float* b2S = (const float*)d_in[10];
    const float* W1B = (const float*)d_in[11];
    const float* b1B = (const float*)d_in[12];
    const float* W2B = (const float*)d_in[13];
    const float* b2B = (const float*)d_in[14];
    const float* WgA = (const float*)d_in[15];
    const float* bgA = (const float*)d_in[16];
    const float* WgB = (const float*)d_in[17];
    const float* bgB = (const float*)d_in[18];
    const float* WgS = (const float*)d_in[19];
    const float* bgS = (const float*)d_in[20];
    float* out = (float*)d_out;

    cudaFuncSetAttribute(xsplit_gates_kernel, cudaFuncAttributeMaxDynamicSharedMemorySize, 12 * 1024 * 4);
    cudaFuncSetAttribute(phase1_mma_kernel,   cudaFuncAttributeMaxDynamicSharedMemorySize, P1_SMEM);
    cudaFuncSetAttribute(phase2_mma_kernel,   cudaFuncAttributeMaxDynamicSharedMemorySize, P2_SMEM);

    wsplit_kernel<<<3072, 256>>>(W1A, W1S, W1B);
    w2split_kernel<<<768, 256>>>(W2A, W2S, W2B);
    xsplit_gates_kernel<<<dim3(2048, 3), 256, 12 * 1024 * 4>>>(xA, xS, xB, WgA, WgS, WgB, bgA, bgS, bgB);
    phase1_mma_kernel<<<dim3(2, 128, 3), 256, P1_SMEM>>>(b1A, b1S, b1B);
    phase2_mma_kernel<<<dim3(BSZ / 64, 6), 256, P2_SMEM>>>(b2A, b2S, b2B, out);
}